// round 6
// baseline (speedup 1.0000x reference)
#include <cuda_runtime.h>
#include <math.h>

#define NBATCH 2048

// ---- image layout: phase-split, zero halo, conflict-free ----
// row ry = y+2 (0..66), phase ph = xp&3, slot = ph*18 + (xp>>2), xp = x+2 (0..67)
#define IMROW 74                    // 4*74 = 296 ≡ 8 mod 32 -> oy groups hit banks {0,8,16,24}
#define IMCH  (67 * IMROW)          // 4958
#define SMEM_FLOATS (3 * IMCH)      // 14874 floats = 59496 bytes -> 3 CTAs/SM

// aliases in the image region (dead after conv1):
#define S_C1   0                    // conv1 out [10][15][16] = 2400
#define S_W2P  2400                 // conv2 weights padded [16][10][5][8] = 6400
#define S_P1P  8800                 // pool1 out zero-padded [10][11][12] = 1320
#define S_C2   10120                // conv2 out [16][4][4] = 256
#define S_FL   10376                // flat 64

__constant__ float cw1[3630];       // conv1 weights, natural [f][c][ky][kx]

__device__ __forceinline__ float leaky(float v) { return v > 0.f ? v : 0.01f * v; }

__device__ __forceinline__ unsigned long long pack2(float lo, float hi) {
    unsigned long long r;
    asm("mov.b64 %0, {%1, %2};" : "=l"(r) : "f"(lo), "f"(hi));
    return r;
}
__device__ __forceinline__ void fma2(unsigned long long& d, unsigned long long a,
                                     unsigned long long b) {
    asm("fma.rn.f32x2 %0, %1, %2, %0;" : "+l"(d) : "l"(a), "l"(b));
}
__device__ __forceinline__ void unpack2(unsigned long long v, float& lo, float& hi) {
    asm("mov.b64 {%0, %1}, %2;" : "=f"(lo), "=f"(hi) : "l"(v));
}

__global__ void __launch_bounds__(256, 3)
cnn_kernel(const float* __restrict__ im,
           const float* __restrict__ w2,
           const float* __restrict__ b2,
           const float* __restrict__ lw,
           const float* __restrict__ lb,
           float* __restrict__ out)
{
    extern __shared__ float sm[];
    const int b   = blockIdx.x;
    const int tid = threadIdx.x;

    // ---- zero whole image region (halo correctness), then scatter ----
    for (int i = tid; i < 3 * IMCH; i += 256) sm[i] = 0.f;
    __syncthreads();

    {
        const float2* gim = (const float2*)(im + (size_t)b * 12288);
        for (int i = tid; i < 6144; i += 256) {
            float2 v = gim[i];
            int fi = i << 1;
            int c  = fi >> 12;
            int y  = (fi & 4095) >> 6;
            int x  = fi & 63;
            int base = c * IMCH + (y + 2) * IMROW;
            int xp = x + 2;
            sm[base + (xp & 3) * 18 + (xp >> 2)] = v.x;
            xp++;
            sm[base + (xp & 3) * 18 + (xp >> 2)] = v.y;
        }
    }

    // graph half is analytically constant: softmax == 0.05 (verified exact R1-R4)
    if (tid < 20)
        out[b * 20 + tid] = 0.05f;

    __syncthreads();

    // ---- conv1 (11x11, s4, p2): 15x15 out, 10 filters, 2 pixels/thread ----
    // thread t<120: oy = t>>3 (0..14), pr = t&7; pixels (oy,pr) and (oy,pr+8)
    // weights from __constant__ (uniform LDCU, no L1 traffic), filter-pair f32x2:
    //   acc[fp][px] 64-bit = {filter 2fp, filter 2fp+1} partial sums for pixel px
    const int oy = tid >> 3, pr = tid & 7;
    const bool c1act = (tid < 120);
    unsigned long long acc[5][2];
    #pragma unroll
    for (int fp = 0; fp < 5; fp++) { acc[fp][0] = 0ull; acc[fp][1] = 0ull; }

    if (c1act) {
        #pragma unroll 1
        for (int c = 0; c < 3; c++) {
            #pragma unroll 1
            for (int ky = 0; ky < 11; ky++) {
                const float* ip = &sm[c * IMCH + (4 * oy + ky) * IMROW + pr];
                const int wb = (c * 11 + ky) * 11;   // + f*363 + k
                #pragma unroll
                for (int k = 0; k < 11; k++) {
                    const int slot = (k & 3) * 18 + (k >> 2);
                    float x1 = ip[slot];
                    float x2 = ip[slot + 8];         // pr==7 reads zero pad lane (discarded)
                    unsigned long long xp1 = pack2(x1, x1);
                    unsigned long long xp2 = pack2(x2, x2);
                    #pragma unroll
                    for (int fp = 0; fp < 5; fp++) {
                        float wa = cw1[(2 * fp) * 363 + wb + k];
                        float wc = cw1[(2 * fp + 1) * 363 + wb + k];
                        unsigned long long wpk = pack2(wa, wc);
                        fma2(acc[fp][0], xp1, wpk);
                        fma2(acc[fp][1], xp2, wpk);
                    }
                }
            }
        }
    }
    __syncthreads();   // image reads done; region reusable

    if (c1act) {
        #pragma unroll
        for (int fp = 0; fp < 5; fp++) {
            float v0, v1;
            unpack2(acc[fp][0], v0, v1);
            sm[S_C1 + ((2 * fp) * 15 + oy) * 16 + pr]     = leaky(v0);
            sm[S_C1 + ((2 * fp + 1) * 15 + oy) * 16 + pr] = leaky(v1);
            if (pr < 7) {
                unpack2(acc[fp][1], v0, v1);
                sm[S_C1 + ((2 * fp) * 15 + oy) * 16 + pr + 8]     = leaky(v0);
                sm[S_C1 + ((2 * fp + 1) * 15 + oy) * 16 + pr + 8] = leaky(v1);
            }
        }
    }
    // stage conv2 weights padded [f][c][ky][8]
    for (int i = tid; i < 4000; i += 256) {
        int kx = i % 5; int t = i / 5;
        int ky = t % 5; t /= 5;
        int c  = t % 10; int f = t / 10;
        sm[S_W2P + (((f * 10 + c) * 5) + ky) * 8 + kx] = w2[i];
    }
    // zero-fill padded pool1 buffer
    for (int i = tid; i < 1320; i += 256)
        sm[S_P1P + i] = 0.f;
    __syncthreads();

    // ---- maxpool 3x3 s2: 15x15 -> 7x7, write into zero-padded [10][11][12] ----
    for (int i = tid; i < 490; i += 256) {
        int f = i / 49, r = i % 49;
        int py = r / 7, px = r % 7;
        float m = -1e30f;
        #pragma unroll
        for (int dy = 0; dy < 3; dy++)
            #pragma unroll
            for (int dx = 0; dx < 3; dx++)
                m = fmaxf(m, sm[S_C1 + (f * 15 + (2 * py + dy)) * 16 + (2 * px + dx)]);
        sm[S_P1P + (f * 11 + py + 2) * 12 + px + 2] = m;
    }
    __syncthreads();

    // ---- conv2 (5x5, s2, p2): 7x7 -> 4x4, 10 -> 16 ch, guard-free ----
    {
        int f   = tid >> 4;
        int r   = tid & 15;
        int oy2 = r >> 2;
        int ox2 = r & 3;
        float a = b2[f];
        #pragma unroll 1
        for (int c = 0; c < 10; c++) {
            #pragma unroll
            for (int ky = 0; ky < 5; ky++) {
                const float* prow = &sm[S_P1P + (c * 11 + 2 * oy2 + ky) * 12 + 2 * ox2];
                const float4 wv = *(const float4*)&sm[S_W2P + ((f * 10 + c) * 5 + ky) * 8];
                const float  w4 = sm[S_W2P + ((f * 10 + c) * 5 + ky) * 8 + 4];
                a = fmaf(prow[0], wv.x, a);
                a = fmaf(prow[1], wv.y, a);
                a = fmaf(prow[2], wv.z, a);
                a = fmaf(prow[3], wv.w, a);
                a = fmaf(prow[4], w4,  a);
            }
        }
        sm[S_C2 + f * 16 + oy2 * 4 + ox2] = leaky(a);
    }
    __syncthreads();

    // ---- maxpool 2x2 s2: 4x4 -> 2x2, flatten ----
    if (tid < 64) {
        int f = tid >> 2, py = (tid >> 1) & 1, px = tid & 1;
        float m = sm[S_C2 + f * 16 + (2 * py) * 4 + (2 * px)];
        m = fmaxf(m, sm[S_C2 + f * 16 + (2 * py) * 4 + (2 * px + 1)]);
        m = fmaxf(m, sm[S_C2 + f * 16 + (2 * py + 1) * 4 + (2 * px)]);
        m = fmaxf(m, sm[S_C2 + f * 16 + (2 * py + 1) * 4 + (2 * px + 1)]);
        sm[S_FL + tid] = m;   // flat index == tid
    }
    __syncthreads();

    // ---- linear 64 -> 2 + sigmoid ----
    if (tid < 2) {
        float a = lb[tid];
        #pragma unroll
        for (int k = 0; k < 64; k++)
            a = fmaf(sm[S_FL + k], lw[tid * 64 + k], a);
        out[NBATCH * 20 + b * 2 + tid] = 1.f / (1.f + __expf(-a));
    }
}

extern "C" void kernel_launch(void* const* d_in, const int* in_sizes, int n_in,
                              void* d_out, int out_size)
{
    (void)in_sizes; (void)n_in; (void)out_size;
    const float* im = (const float*)d_in[0];
    // d_in[1] = x, d_in[2] = edge_index : dead (graph output is constant 0.05)
    const float* w1 = (const float*)d_in[3];
    const float* w2 = (const float*)d_in[4];
    const float* b2 = (const float*)d_in[5];
    const float* lw = (const float*)d_in[6];
    const float* lb = (const float*)d_in[7];
    float* out = (float*)d_out;

    // refresh conv1 weights in constant memory (D2D async copy: graph-capturable)
    cudaMemcpyToSymbolAsync(cw1, w1, 3630 * sizeof(float), 0,
                            cudaMemcpyDeviceToDevice, 0);

    cudaFuncSetAttribute(cnn_kernel, cudaFuncAttributeMaxDynamicSharedMemorySize,
                         SMEM_FLOATS * sizeof(float));
    cnn_kernel<<<NBATCH, 256, SMEM_FLOATS * sizeof(float)>>>(im, w2, b2, lw, lb, out);
}

// round 7
// speedup vs baseline: 2.0378x; 2.0378x over previous
#include <cuda_runtime.h>
#include <math.h>

#define NBATCH 2048

// ---- image layout: phase-split, zero halo, conflict-free ----
// row ry = y+2 (0..66), phase ph = xp&3, slot = ph*18 + (xp>>2), xp = x+2 (0..67)
#define IMROW 74                    // 4*74 = 296 ≡ 8 mod 32 -> oy groups hit banks {0,8,16,24}
#define IMCH  (67 * IMROW)          // 4958
#define S_W1  14876                 // conv1 weights [c][ky][fh][5][12] = 3960 (float4-aligned base)
#define SMEM_FLOATS (S_W1 + 3960)   // 18836 floats = 75344 bytes -> 3 CTAs/SM

// aliases in the image region (dead after conv1):
#define S_C1   0                    // conv1 out [10][15][16] = 2400
#define S_W2P  2400                 // conv2 weights padded [16][10][5][8] = 6400
#define S_P1P  8800                 // pool1 out zero-padded [10][11][12] = 1320
#define S_C2   10120                // conv2 out [16][4][4] = 256
#define S_FL   10376                // flat 64

__device__ __forceinline__ float leaky(float v) { return v > 0.f ? v : 0.01f * v; }

__global__ void __launch_bounds__(256, 3)
cnn_kernel(const float* __restrict__ im,
           const float* __restrict__ w1,
           const float* __restrict__ w2,
           const float* __restrict__ b2,
           const float* __restrict__ lw,
           const float* __restrict__ lb,
           float* __restrict__ out)
{
    extern __shared__ float sm[];
    const int b   = blockIdx.x;
    const int tid = threadIdx.x;

    // ---- zero whole image region (halo correctness), then scatter ----
    for (int i = tid; i < 3 * IMCH; i += 256) sm[i] = 0.f;
    __syncthreads();

    {
        const float2* gim = (const float2*)(im + (size_t)b * 12288);
        for (int i = tid; i < 6144; i += 256) {
            float2 v = gim[i];
            int fi = i << 1;
            int c  = fi >> 12;
            int y  = (fi & 4095) >> 6;
            int x  = fi & 63;
            int base = c * IMCH + (y + 2) * IMROW;
            int xp = x + 2;
            sm[base + (xp & 3) * 18 + (xp >> 2)] = v.x;
            xp++;
            sm[base + (xp & 3) * 18 + (xp >> 2)] = v.y;
        }
    }
    // conv1 weights: [f][c][ky][kx] -> [c][ky][fh][f'][12]  (f = fh*5 + f')
    for (int i = tid; i < 3630; i += 256) {
        int f   = i / 363;
        int rem = i % 363;
        int c   = rem / 121;
        int r2  = rem % 121;
        int ky  = r2 / 11;
        int kx  = r2 % 11;
        sm[S_W1 + ((((c * 11 + ky) * 2 + (f / 5)) * 5) + (f % 5)) * 12 + kx] = w1[i];
    }

    // graph half is analytically constant: softmax == 0.05 (verified exact R1-R6)
    if (tid < 20)
        out[b * 20 + tid] = 0.05f;

    __syncthreads();

    // ---- conv1 (11x11, s4, p2): 15x15 out, 10 filters ----
    // thread t<120: oy = t>>3 (0..14), pr = (t>>1)&3, fh = t&1
    // pixels: cols {pr, pr+4, pr+8, pr+12}; filters: fh*5 .. fh*5+4
    // per-lane smem traffic per (c,ky): 4 input + 5 weight scalars per k
    const int oy = tid >> 3, pr = (tid >> 1) & 3, fh = tid & 1;
    const bool c1act = (tid < 120);
    float acc[5][4];
    #pragma unroll
    for (int f = 0; f < 5; f++)
        #pragma unroll
        for (int j = 0; j < 4; j++) acc[f][j] = 0.f;

    if (c1act) {
        #pragma unroll 1
        for (int c = 0; c < 3; c++) {
            #pragma unroll 1
            for (int ky = 0; ky < 11; ky++) {
                const float* ip = &sm[c * IMCH + (4 * oy + ky) * IMROW + pr];
                const float* wr = &sm[S_W1 + (((c * 11 + ky) * 2 + fh) * 5) * 12];
                #pragma unroll
                for (int k = 0; k < 11; k++) {
                    const int sl = (k & 3) * 18 + (k >> 2);
                    float x0 = ip[sl];
                    float x1 = ip[sl + 4];
                    float x2 = ip[sl + 8];
                    float x3 = ip[sl + 12];   // col pr+12 (garbage when pr==3; discarded)
                    #pragma unroll
                    for (int f = 0; f < 5; f++) {
                        float w = wr[f * 12 + k];
                        acc[f][0] = fmaf(x0, w, acc[f][0]);
                        acc[f][1] = fmaf(x1, w, acc[f][1]);
                        acc[f][2] = fmaf(x2, w, acc[f][2]);
                        acc[f][3] = fmaf(x3, w, acc[f][3]);
                    }
                }
            }
        }
    }
    __syncthreads();   // image reads done; region reusable

    if (c1act) {
        #pragma unroll
        for (int f = 0; f < 5; f++) {
            const int fg = fh * 5 + f;
            #pragma unroll
            for (int j = 0; j < 4; j++) {
                int ox = pr + 4 * j;
                if (ox < 15)
                    sm[S_C1 + (fg * 15 + oy) * 16 + ox] = leaky(acc[f][j]);
            }
        }
    }
    // stage conv2 weights padded [f][c][ky][8]
    for (int i = tid; i < 4000; i += 256) {
        int kx = i % 5; int t = i / 5;
        int ky = t % 5; t /= 5;
        int c  = t % 10; int f = t / 10;
        sm[S_W2P + (((f * 10 + c) * 5) + ky) * 8 + kx] = w2[i];
    }
    // zero-fill padded pool1 buffer
    for (int i = tid; i < 1320; i += 256)
        sm[S_P1P + i] = 0.f;
    __syncthreads();

    // ---- maxpool 3x3 s2: 15x15 -> 7x7, write into zero-padded [10][11][12] ----
    for (int i = tid; i < 490; i += 256) {
        int f = i / 49, r = i % 49;
        int py = r / 7, px = r % 7;
        float m = -1e30f;
        #pragma unroll
        for (int dy = 0; dy < 3; dy++)
            #pragma unroll
            for (int dx = 0; dx < 3; dx++)
                m = fmaxf(m, sm[S_C1 + (f * 15 + (2 * py + dy)) * 16 + (2 * px + dx)]);
        sm[S_P1P + (f * 11 + py + 2) * 12 + px + 2] = m;
    }
    __syncthreads();

    // ---- conv2 (5x5, s2, p2): 7x7 -> 4x4, 10 -> 16 ch, guard-free ----
    {
        int f   = tid >> 4;
        int r   = tid & 15;
        int oy2 = r >> 2;
        int ox2 = r & 3;
        float a = b2[f];
        #pragma unroll 1
        for (int c = 0; c < 10; c++) {
            #pragma unroll
            for (int ky = 0; ky < 5; ky++) {
                const float* prow = &sm[S_P1P + (c * 11 + 2 * oy2 + ky) * 12 + 2 * ox2];
                const float4 wv = *(const float4*)&sm[S_W2P + ((f * 10 + c) * 5 + ky) * 8];
                const float  w4 = sm[S_W2P + ((f * 10 + c) * 5 + ky) * 8 + 4];
                a = fmaf(prow[0], wv.x, a);
                a = fmaf(prow[1], wv.y, a);
                a = fmaf(prow[2], wv.z, a);
                a = fmaf(prow[3], wv.w, a);
                a = fmaf(prow[4], w4,  a);
            }
        }
        sm[S_C2 + f * 16 + oy2 * 4 + ox2] = leaky(a);
    }
    __syncthreads();

    // ---- maxpool 2x2 s2: 4x4 -> 2x2, flatten ----
    if (tid < 64) {
        int f = tid >> 2, py = (tid >> 1) & 1, px = tid & 1;
        float m = sm[S_C2 + f * 16 + (2 * py) * 4 + (2 * px)];
        m = fmaxf(m, sm[S_C2 + f * 16 + (2 * py) * 4 + (2 * px + 1)]);
        m = fmaxf(m, sm[S_C2 + f * 16 + (2 * py + 1) * 4 + (2 * px)]);
        m = fmaxf(m, sm[S_C2 + f * 16 + (2 * py + 1) * 4 + (2 * px + 1)]);
        sm[S_FL + tid] = m;   // flat index == tid
    }
    __syncthreads();

    // ---- linear 64 -> 2 + sigmoid ----
    if (tid < 2) {
        float a = lb[tid];
        #pragma unroll
        for (int k = 0; k < 64; k++)
            a = fmaf(sm[S_FL + k], lw[tid * 64 + k], a);
        out[NBATCH * 20 + b * 2 + tid] = 1.f / (1.f + __expf(-a));
    }
}

extern "C" void kernel_launch(void* const* d_in, const int* in_sizes, int n_in,
                              void* d_out, int out_size)
{
    (void)in_sizes; (void)n_in; (void)out_size;
    const float* im = (const float*)d_in[0];
    // d_in[1] = x, d_in[2] = edge_index : dead (graph output is constant 0.05)
    const float* w1 = (const float*)d_in[3];
    const float* w2 = (const float*)d_in[4];
    const float* b2 = (const float*)d_in[5];
    const float* lw = (const float*)d_in[6];
    const float* lb = (const float*)d_in[7];
    float* out = (float*)d_out;

    cudaFuncSetAttribute(cnn_kernel, cudaFuncAttributeMaxDynamicSharedMemorySize,
                         SMEM_FLOATS * sizeof(float));
    cnn_kernel<<<NBATCH, 256, SMEM_FLOATS * sizeof(float)>>>(im, w1, w2, b2, lw, lb, out);
}